// round 15
// baseline (speedup 1.0000x reference)
#include <cuda_runtime.h>
#include <cuda_bf16.h>
#include <math.h>

#define LNUM   102
#define LSTART 100
#define LPAD   104
#define QSTR   128                // padded q_sh row (unconditional STS)
#define NT     128
#define MAXB   1024
#define SCALE  4.0f
#define RMASK  31                 // exact renorm every 32 steps

__device__ int   g_perm[MAXB];
__device__ float g_vecF[MAXB][LPAD];
__device__ float g_vecB[MAXB][LPAD];
__device__ float g_CF[MAXB];
__device__ float g_CB[MAXB];

typedef __nv_bfloat162 bf2;

// ---------- counting sort (descending length), warp-scan version ----------
__global__ void sort_kernel(const int* __restrict__ lens, int B, int T) {
    __shared__ int hist[513];
    __shared__ int off[520];
    const int tid = threadIdx.x;          // 1024 threads
    if (tid < 513) hist[tid] = 0;
    __syncthreads();
    int myLen = 0;
    if (tid < B) {
        myLen = lens[tid];
        if (myLen < 0) myLen = 0;
        if (myLen > T) myLen = T;
        if (myLen > 512) myLen = 512;
        atomicAdd(&hist[myLen], 1);
    }
    __syncthreads();
    // warp 0: off[v] = #elements with length > v  (suffix sum over 513 bins)
    if (tid < 32) {
        // lane i owns r = 17*i .. 17*i+16, where value v = 512 - r
        int pre[17];
        int acc = 0;
        #pragma unroll
        for (int s = 0; s < 17; ++s) {
            const int r = 17 * tid + s;
            pre[s] = acc;                            // exclusive within lane
            if (r < 513) acc += hist[512 - r];
        }
        // exclusive warp scan of lane totals
        int excl = acc;
        #pragma unroll
        for (int o = 1; o < 32; o <<= 1) {
            int v = __shfl_up_sync(0xffffffffu, excl, o);
            if (tid >= o) excl += v;
        }
        excl -= acc;                                 // exclusive prefix
        #pragma unroll
        for (int s = 0; s < 17; ++s) {
            const int r = 17 * tid + s;
            if (r < 513) off[512 - r] = excl + pre[s];
        }
    }
    __syncthreads();
    if (tid < B) {
        int pos = atomicAdd(&off[myLen], 1);
        g_perm[pos] = tid;
    }
}

// ---------- half-chain kernel: forward (E) or backward (E^T), bf16 engine ----------
__global__ __launch_bounds__(NT, 4)
void crf_half_kernel(const float* __restrict__ logits,
                     const float* __restrict__ trans,
                     const int*   __restrict__ lens,
                     int T)
{
    const int  j    = threadIdx.x;
    const int  rank = blockIdx.x >> 1;
    const bool bwd  = (blockIdx.x & 1) != 0;
    const int  b    = g_perm[rank];

    __shared__ __align__(16) __nv_bfloat16 q_sh[2][QSTR];

    int len = lens[b];
    if (len > T) len = T;
    if (len < 0) len = 0;
    const int m  = len >> 1;
    const int n  = bwd ? (len - m) : m;       // steps this half runs
    const int nv = bwd ? (n - 1) : n;         // # valid logit reads in-loop

    // E fragment: fwd rows of E, bwd rows of E^T — 52 bf16x2 (pads = 0)
    bf2 E2[52];
    #pragma unroll
    for (int mm = 0; mm < 52; ++mm) {
        float a = 0.f, c = 0.f;
        const int k = 2 * mm;
        if (j < LNUM) {
            if (!bwd) {
                const float* tr = trans + (size_t)j * LNUM;
                if (k + 0 < LNUM) a = __expf(tr[k + 0]);
                if (k + 1 < LNUM) c = __expf(tr[k + 1]);
            } else {
                if (k + 0 < LNUM) a = __expf(trans[(size_t)(k + 0) * LNUM + j]);
                if (k + 1 < LNUM) c = __expf(trans[(size_t)(k + 1) * LNUM + j]);
            }
        }
        E2[mm] = __floats2bfloat162_rn(a, c);   // (x=k, y=k+1)
    }

    const float* lg = logits + (size_t)b * T * LNUM;

    // init vector (pad threads j>=104 compute harmless values; E2=0 kills them)
    float q;
    if (!bwd) {
        q = (j == LSTART) ? 1.f : 0.f;
    } else {
        float vstop = (j < LNUM) ? __expf(trans[(size_t)(LNUM - 1) * LNUM + j]) : 0.f;
        if (len > 0) {
            float lgl = (j < LNUM) ? __ldcs(&lg[(size_t)(len - 1) * LNUM + j]) : SCALE;
            q = __expf(lgl - SCALE) * vstop;
        } else {
            q = vstop;
        }
    }
    q_sh[0][j] = __float2bfloat16(q);
    q_sh[1][j] = __float2bfloat16(0.f);

    // logit addressing: step s reads row (fwd: s) / (bwd: len-2-s)
    const ptrdiff_t strd = bwd ? -(ptrdiff_t)LNUM : (ptrdiff_t)LNUM;
    const ptrdiff_t row0 = bwd ? (ptrdiff_t)(len - 2) * LNUM : 0;
    const float* lgcol = lg + row0 + j;

    float C = 0.f;

    // depth-4 register logit pipeline (streaming loads: used once)
    float lgq[4];
    #pragma unroll
    for (int u = 0; u < 4; ++u)
        lgq[u] = (u < nv && j < LNUM) ? __ldcs(&lgcol[strd * u]) : SCALE;

    __syncthreads();

    for (int tc = 0; tc < n; tc += 4) {
        // prefetch next chunk (MLP=4)
        float lgn[4];
        #pragma unroll
        for (int u = 0; u < 4; ++u) {
            const int sl = tc + 4 + u;
            lgn[u] = (sl < nv && j < LNUM) ? __ldcs(&lgcol[strd * sl]) : SCALE;
        }

        const bool chunk_max = ((tc & RMASK) == 0) && (tc > 0);

        #pragma unroll
        for (int u = 0; u < 4; ++u) {
            const int t = tc + u;
            if (t >= n) break;                  // uniform across block

            const float el = __expf(lgq[u] - SCALE);
            const bool do_max = chunk_max && (u == 0);

            // y[j] = sum_k E[j,k] * q[k] — 13 LDS.128 + 52 HFMA2 (bf16x2)
            const uint4* ps = reinterpret_cast<const uint4*>(q_sh[t & 1]);
            uint4 v = ps[0];
            bf2 v0 = *reinterpret_cast<bf2*>(&v.x);
            bf2 v1 = *reinterpret_cast<bf2*>(&v.y);
            bf2 v2 = *reinterpret_cast<bf2*>(&v.z);
            bf2 v3 = *reinterpret_cast<bf2*>(&v.w);
            bf2 a0 = __hmul2(E2[0], v0);
            bf2 a1 = __hmul2(E2[1], v1);
            bf2 a2 = __hmul2(E2[2], v2);
            bf2 a3 = __hmul2(E2[3], v3);
            bf2 mx = __floats2bfloat162_rn(0.f, 0.f);
            if (do_max)
                mx = __hmax2(__hmax2(v0, v1), __hmax2(v2, v3));
            #pragma unroll
            for (int mm = 1; mm < 13; ++mm) {
                uint4 w = ps[mm];
                bf2 w0 = *reinterpret_cast<bf2*>(&w.x);
                bf2 w1 = *reinterpret_cast<bf2*>(&w.y);
                bf2 w2 = *reinterpret_cast<bf2*>(&w.z);
                bf2 w3 = *reinterpret_cast<bf2*>(&w.w);
                a0 = __hfma2(E2[4 * mm + 0], w0, a0);
                a1 = __hfma2(E2[4 * mm + 1], w1, a1);
                a2 = __hfma2(E2[4 * mm + 2], w2, a2);
                a3 = __hfma2(E2[4 * mm + 3], w3, a3);
                if (do_max)
                    mx = __hmax2(mx, __hmax2(__hmax2(w0, w1), __hmax2(w2, w3)));
            }
            bf2 s2 = __hadd2(__hadd2(a0, a1), __hadd2(a2, a3));
            float y = __low2float(s2) + __high2float(s2);

            if (do_max) {                       // uniform exact renorm every 32 steps
                const float M = fmaxf(
                    fmaxf(__low2float(mx), __high2float(mx)), 1e-30f);
                y *= __fdividef(1.f, M);
                C += __logf(M);
            }

            q = el * y;                         // pads: E2=0 -> y=0 -> q=0
            q_sh[(t + 1) & 1][j] = __float2bfloat16(q);   // unconditional STS
            __syncthreads();
        }

        #pragma unroll
        for (int u = 0; u < 4; ++u) lgq[u] = lgn[u];
    }

    // publish this half's vector + scale constant
    if (j < LPAD) {
        if (!bwd) g_vecF[b][j] = q;
        else      g_vecB[b][j] = q;
    }
    if (j == 0) {
        const float Ctot = C + SCALE * (float)n;
        if (!bwd) g_CF[b] = Ctot;
        else      g_CB[b] = Ctot;
    }
}

// ---------- combine: out[b] = CF + CB + log( f . g ) ----------
__global__ void combine_kernel(float* __restrict__ out, int B)
{
    const int warp = (blockIdx.x * blockDim.x + threadIdx.x) >> 5;
    const int l    = threadIdx.x & 31;
    if (warp >= B) return;

    double s = 0.0;
    for (int k = l; k < LPAD; k += 32)
        s += (double)g_vecF[warp][k] * (double)g_vecB[warp][k];
    #pragma unroll
    for (int o = 16; o; o >>= 1)
        s += __shfl_xor_sync(0xffffffffu, s, o);
    if (l == 0)
        out[warp] = g_CF[warp] + g_CB[warp] + (float)log(s);
}

extern "C" void kernel_launch(void* const* d_in, const int* in_sizes, int n_in,
                              void* d_out, int out_size)
{
    const float* logits = (const float*)d_in[0];   // [B, T, L] f32
    const float* trans  = (const float*)d_in[1];   // [L, L]    f32
    const int*   lens   = (const int*)d_in[2];     // [B]       i32
    float*       out    = (float*)d_out;           // [B]       f32

    const int B = in_sizes[2];
    const int T = in_sizes[0] / (B * LNUM);

    sort_kernel<<<1, 1024>>>(lens, B, T);
    crf_half_kernel<<<2 * B, NT>>>(logits, trans, lens, T);
    combine_kernel<<<(B * 32 + NT - 1) / NT, NT>>>(out, B);
}

// round 16
// speedup vs baseline: 1.0439x; 1.0439x over previous
#include <cuda_runtime.h>
#include <cuda_bf16.h>
#include <math.h>

#define LNUM   102
#define LSTART 100
#define LPAD   104
#define NT     128
#define MAXB   1024
#define SCALE  4.0f
#define RMASK  31                 // exact renorm every 32 steps

__device__ int   g_perm[MAXB];
__device__ float g_vecF[MAXB][LPAD];
__device__ float g_vecB[MAXB][LPAD];
__device__ float g_CF[MAXB];
__device__ float g_CB[MAXB];

typedef __nv_bfloat162 bf2;

// ---------- counting sort (descending length), warp-scan version ----------
__global__ void sort_kernel(const int* __restrict__ lens, int B, int T) {
    __shared__ int hist[513];
    __shared__ int off[520];
    const int tid = threadIdx.x;          // 1024 threads
    if (tid < 513) hist[tid] = 0;
    __syncthreads();
    int myLen = 0;
    if (tid < B) {
        myLen = lens[tid];
        if (myLen < 0) myLen = 0;
        if (myLen > T) myLen = T;
        if (myLen > 512) myLen = 512;
        atomicAdd(&hist[myLen], 1);
    }
    __syncthreads();
    // warp 0: off[v] = #elements with length > v  (suffix sum over 513 bins)
    if (tid < 32) {
        int pre[17];
        int acc = 0;
        #pragma unroll
        for (int s = 0; s < 17; ++s) {
            const int r = 17 * tid + s;
            pre[s] = acc;                            // exclusive within lane
            if (r < 513) acc += hist[512 - r];
        }
        int excl = acc;
        #pragma unroll
        for (int o = 1; o < 32; o <<= 1) {
            int v = __shfl_up_sync(0xffffffffu, excl, o);
            if (tid >= o) excl += v;
        }
        excl -= acc;                                 // exclusive prefix
        #pragma unroll
        for (int s = 0; s < 17; ++s) {
            const int r = 17 * tid + s;
            if (r < 513) off[512 - r] = excl + pre[s];
        }
    }
    __syncthreads();
    if (tid < B) {
        int pos = atomicAdd(&off[myLen], 1);
        g_perm[pos] = tid;
    }
}

// ---------- half-chain kernel: forward (E) or backward (E^T), bf16 engine ----------
__global__ __launch_bounds__(NT, 4)
void crf_half_kernel(const float* __restrict__ logits,
                     const float* __restrict__ trans,
                     const int*   __restrict__ lens,
                     int T)
{
    const int  j    = threadIdx.x;
    const int  rank = blockIdx.x >> 1;
    const bool bwd  = (blockIdx.x & 1) != 0;
    const int  b    = g_perm[rank];

    __shared__ __align__(16) __nv_bfloat16 q_sh[2][LPAD];

    int len = lens[b];
    if (len > T) len = T;
    if (len < 0) len = 0;
    const int m  = len >> 1;
    const int n  = bwd ? (len - m) : m;       // steps this half runs
    const int nv = bwd ? (n - 1) : n;         // # valid logit reads in-loop

    // E fragment: fwd rows of E, bwd rows of E^T — 52 bf16x2 (pads = 0)
    bf2 E2[52];
    #pragma unroll
    for (int mm = 0; mm < 52; ++mm) {
        float a = 0.f, c = 0.f;
        const int k = 2 * mm;
        if (j < LNUM) {
            if (!bwd) {
                const float* tr = trans + (size_t)j * LNUM;
                if (k + 0 < LNUM) a = __expf(tr[k + 0]);
                if (k + 1 < LNUM) c = __expf(tr[k + 1]);
            } else {
                if (k + 0 < LNUM) a = __expf(trans[(size_t)(k + 0) * LNUM + j]);
                if (k + 1 < LNUM) c = __expf(trans[(size_t)(k + 1) * LNUM + j]);
            }
        }
        E2[mm] = __floats2bfloat162_rn(a, c);   // (x=k, y=k+1)
    }

    const float* lg = logits + (size_t)b * T * LNUM;

    // init vector
    float q;
    if (!bwd) {
        q = (j == LSTART) ? 1.f : 0.f;
    } else {
        float vstop = (j < LNUM) ? __expf(trans[(size_t)(LNUM - 1) * LNUM + j]) : 0.f;
        if (len > 0) {
            float lgl = (j < LNUM) ? __ldcs(&lg[(size_t)(len - 1) * LNUM + j]) : SCALE;
            q = __expf(lgl - SCALE) * vstop;
        } else {
            q = vstop;
        }
    }
    if (j < LPAD) {
        q_sh[0][j] = __float2bfloat16(q);
        q_sh[1][j] = __float2bfloat16(0.f);
    }

    // logit addressing: step s reads row (fwd: s) / (bwd: len-2-s)
    const ptrdiff_t strd = bwd ? -(ptrdiff_t)LNUM : (ptrdiff_t)LNUM;
    const ptrdiff_t row0 = bwd ? (ptrdiff_t)(len - 2) * LNUM : 0;
    const float* lgcol = lg + row0 + j;

    float C = 0.f;

    // depth-4 register logit pipeline (streaming loads: used once)
    float lgq[4];
    #pragma unroll
    for (int u = 0; u < 4; ++u)
        lgq[u] = (u < nv && j < LNUM) ? __ldcs(&lgcol[strd * u]) : SCALE;

    __syncthreads();

    for (int tc = 0; tc < n; tc += 4) {
        // prefetch next chunk (MLP=4)
        float lgn[4];
        #pragma unroll
        for (int u = 0; u < 4; ++u) {
            const int sl = tc + 4 + u;
            lgn[u] = (sl < nv && j < LNUM) ? __ldcs(&lgcol[strd * sl]) : SCALE;
        }

        #pragma unroll
        for (int u = 0; u < 4; ++u) {
            const int t = tc + u;
            if (t >= n) break;                  // uniform across block

            const float el = __expf(lgq[u] - SCALE);
            const bool do_max = ((t & RMASK) == 0) && (t > 0);

            // y[j] = sum_k E[j,k] * q[k] — 13 LDS.128 + 52 HFMA2 (bf16x2)
            const uint4* ps = reinterpret_cast<const uint4*>(q_sh[t & 1]);
            uint4 v = ps[0];
            bf2 v0 = *reinterpret_cast<bf2*>(&v.x);
            bf2 v1 = *reinterpret_cast<bf2*>(&v.y);
            bf2 v2 = *reinterpret_cast<bf2*>(&v.z);
            bf2 v3 = *reinterpret_cast<bf2*>(&v.w);
            bf2 a0 = __hmul2(E2[0], v0);
            bf2 a1 = __hmul2(E2[1], v1);
            bf2 a2 = __hmul2(E2[2], v2);
            bf2 a3 = __hmul2(E2[3], v3);
            bf2 mx = __floats2bfloat162_rn(0.f, 0.f);
            if (do_max)
                mx = __hmax2(__hmax2(v0, v1), __hmax2(v2, v3));
            #pragma unroll
            for (int mm = 1; mm < 13; ++mm) {
                uint4 w = ps[mm];
                bf2 w0 = *reinterpret_cast<bf2*>(&w.x);
                bf2 w1 = *reinterpret_cast<bf2*>(&w.y);
                bf2 w2 = *reinterpret_cast<bf2*>(&w.z);
                bf2 w3 = *reinterpret_cast<bf2*>(&w.w);
                a0 = __hfma2(E2[4 * mm + 0], w0, a0);
                a1 = __hfma2(E2[4 * mm + 1], w1, a1);
                a2 = __hfma2(E2[4 * mm + 2], w2, a2);
                a3 = __hfma2(E2[4 * mm + 3], w3, a3);
                if (do_max)
                    mx = __hmax2(mx, __hmax2(__hmax2(w0, w1), __hmax2(w2, w3)));
            }
            bf2 s2 = __hadd2(__hadd2(a0, a1), __hadd2(a2, a3));
            float y = __low2float(s2) + __high2float(s2);

            if (do_max) {                       // uniform exact renorm every 32 steps
                const float M = fmaxf(
                    fmaxf(__low2float(mx), __high2float(mx)), 1e-30f);
                y *= __fdividef(1.f, M);
                C += __logf(M);
            }

            q = el * y;                         // pads: E2=0 -> y=0 -> q=0
            if (j < LPAD) q_sh[(t + 1) & 1][j] = __float2bfloat16(q);
            __syncthreads();
        }

        #pragma unroll
        for (int u = 0; u < 4; ++u) lgq[u] = lgn[u];
    }

    // publish this half's vector + scale constant
    if (j < LPAD) {
        if (!bwd) g_vecF[b][j] = q;
        else      g_vecB[b][j] = q;
    }
    if (j == 0) {
        const float Ctot = C + SCALE * (float)n;
        if (!bwd) g_CF[b] = Ctot;
        else      g_CB[b] = Ctot;
    }
}

// ---------- combine: out[b] = CF + CB + log( f . g ) ----------
__global__ void combine_kernel(float* __restrict__ out, int B)
{
    const int warp = (blockIdx.x * blockDim.x + threadIdx.x) >> 5;
    const int l    = threadIdx.x & 31;
    if (warp >= B) return;

    double s = 0.0;
    for (int k = l; k < LPAD; k += 32)
        s += (double)g_vecF[warp][k] * (double)g_vecB[warp][k];
    #pragma unroll
    for (int o = 16; o; o >>= 1)
        s += __shfl_xor_sync(0xffffffffu, s, o);
    if (l == 0)
        out[warp] = g_CF[warp] + g_CB[warp] + (float)log(s);
}

extern "C" void kernel_launch(void* const* d_in, const int* in_sizes, int n_in,
                              void* d_out, int out_size)
{
    const float* logits = (const float*)d_in[0];   // [B, T, L] f32
    const float* trans  = (const float*)d_in[1];   // [L, L]    f32
    const int*   lens   = (const int*)d_in[2];     // [B]       i32
    float*       out    = (float*)d_out;           // [B]       f32

    const int B = in_sizes[2];
    const int T = in_sizes[0] / (B * LNUM);

    sort_kernel<<<1, 1024>>>(lens, B, T);
    crf_half_kernel<<<2 * B, NT>>>(logits, trans, lens, T);
    combine_kernel<<<(B * 32 + NT - 1) / NT, NT>>>(out, B);
}